// round 14
// baseline (speedup 1.0000x reference)
#include <cuda_runtime.h>
#include <cuda_bf16.h>
#include <cuda_fp16.h>

#define HID    64
#define BATCH  16384
#define NSTEPS 100
#define DT     0.01f
#define SPB    32          // samples per block
#define NBLK   512         // BATCH / SPB
#define AP_STRIDE 40       // 32 + 8 pad: (8kt+tg)*40+g -> banks (8tg+g)%32 all distinct

__device__ float g_pA[NBLK];
__device__ float g_pB[NBLK];

__device__ __forceinline__ float exact_tanh(float v) {
    float av = fabsf(v);
    float e  = __expf(-2.0f * av);
    float r  = __fdividef(1.0f - e, 1.0f + e);
    return copysignf(r, v);
}
__device__ __forceinline__ float tanh_ap(float x) {
    float y; asm("tanh.approx.f32 %0, %1;" : "=f"(y) : "f"(x)); return y;
}
__device__ __forceinline__ unsigned pack_hf2(float lo, float hi) {
    __half2 v = __floats2half2_rn(lo, hi);
    return *reinterpret_cast<unsigned*>(&v);
}
__device__ __forceinline__ void mma_f16(float* c,
                                        unsigned a0, unsigned a1, unsigned a2, unsigned a3,
                                        unsigned b0, unsigned b1) {
    asm volatile("mma.sync.aligned.m16n8k16.row.col.f32.f16.f16.f32 "
                 "{%0,%1,%2,%3},{%4,%5,%6,%7},{%8,%9},{%0,%1,%2,%3};"
                 : "+f"(c[0]), "+f"(c[1]), "+f"(c[2]), "+f"(c[3])
                 : "r"(a0), "r"(a1), "r"(a2), "r"(a3), "r"(b0), "r"(b1));
}

__global__ void __launch_bounds__(128) sim_kernel(
    const float* __restrict__ dw,
    const float* __restrict__ X0, const float* __restrict__ R0,
    const float* __restrict__ pW1, const float* __restrict__ pb1,
    const float* __restrict__ pW2, const float* __restrict__ pb2,
    const float* __restrict__ pW3, const float* __restrict__ pb3,
    const float* __restrict__ qW1, const float* __restrict__ qb1,
    const float* __restrict__ qW2, const float* __restrict__ qb2,
    const float* __restrict__ qW3, const float* __restrict__ qb3,
    float* __restrict__ out)
{
    __shared__ __align__(16) float4   sW1q[HID];            // {w_t, w_x, w_r, b1}
    __shared__ __align__(16) unsigned aH[32 * AP_STRIDE];   // f16x2 h [k2][sample]
    __shared__ __align__(16) float    part[SPB * 4];        // [sample][ng] (2 used)
    __shared__ float  ph1[HID], pd1[HID], ptA[HID], ptB[HID];
    __shared__ float  s_p0, s_dp0, s_pi0, s_b3;
    __shared__ float  redA[4], redB[4];

    const int tid  = threadIdx.x;
    const int lane = tid & 31;
    const int w    = tid >> 5;         // 0..3
    const int g    = lane >> 2;
    const int tg   = lane & 3;
    const int mg   = w >> 1;           // m-group: rows 16mg..16mg+15
    const int ng   = w & 1;            // n-group: cols 32ng..32ng+31

    const float x0v = X0[0], r0v = R0[0];

    for (int k = tid; k < HID; k += 128)
        sW1q[k] = make_float4(qW1[k], qW1[HID + k], qW1[2 * HID + k], qb1[k]);
    if (tid == 0) s_b3 = qb3[0];

    // ---- B fragments: W2 as single fp16, persistent in registers ----
    unsigned bH0[4][4], bH1[4][4];
    float b2a[4], b2b[4], w3a[4], w3b[4];
    #pragma unroll
    for (int nt = 0; nt < 4; ++nt) {
        int n = 32 * ng + 8 * nt + g;
        #pragma unroll
        for (int kt = 0; kt < 4; ++kt) {
            int k0 = 16 * kt + 2 * tg;
            bH0[nt][kt] = pack_hf2(qW2[(k0 + 0) * HID + n], qW2[(k0 + 1) * HID + n]);
            bH1[nt][kt] = pack_hf2(qW2[(k0 + 8) * HID + n], qW2[(k0 + 9) * HID + n]);
        }
        int jc = 32 * ng + 8 * nt + 2 * tg;
        b2a[nt] = qb2[jc];     b2b[nt] = qb2[jc + 1];
        w3a[nt] = qW3[jc];     w3b[nt] = qW3[jc + 1];
    }

    // ---- scalar prep (p0, dp0, pi0), exact tanh ----
    if (tid < HID) {
        int j = tid;
        float a = pW1[HID + j] * x0v + pW1[2 * HID + j] * r0v + pb1[j];
        float h = exact_tanh(a);
        ph1[j] = h;
        pd1[j] = (1.0f - h * h) * pW1[HID + j];
        float aq = qW1[HID + j] * x0v + qW1[2 * HID + j] * r0v + qb1[j];
        ptA[j] = exact_tanh(aq);
    }
    __syncthreads();
    float pa = 0.0f, qa = 0.0f, db = 0.0f;
    if (tid < HID) {
        int j = tid;
        float acc = pb2[j], dacc = 0.0f, accq = qb2[j];
        #pragma unroll 16
        for (int k = 0; k < HID; ++k) {
            float wv = pW2[k * HID + j];
            acc  += ph1[k] * wv;
            dacc += pd1[k] * wv;
            accq += ptA[k] * qW2[k * HID + j];
        }
        float h2 = exact_tanh(acc);
        float d2 = (1.0f - h2 * h2) * dacc;
        pa = h2 * pW3[j];
        db = d2 * pW3[j];
        qa = exact_tanh(accq) * qW3[j];
    }
    __syncthreads();
    if (tid < HID) { ph1[tid] = pa; pd1[tid] = qa; ptB[tid] = db; }
    __syncthreads();
    if (tid == 0) {
        float s = pb3[0], sd = 0.0f, sq = qb3[0];
        for (int k = 0; k < HID; ++k) { s += ph1[k]; sd += ptB[k]; sq += pd1[k]; }
        s_p0 = s; s_dp0 = sd; s_pi0 = sq;
    }
    __syncthreads();

    const float p0  = s_p0;
    const float dp0 = s_dp0;
    const float pi0 = s_pi0;
    const float b3v = s_b3;

    const float C_ADT  = 0.05f * 0.01f;
    const float C_STDT = 0.2f * 0.3f * 0.01f;
    const float SIG    = 0.2f;
    const float BEFF   = 0.1f;
    const float C_R1   = 0.02f - 0.5f * 0.1f * 0.1f;
    const float C_P1   = -(0.05f + 0.5f * 0.3f * 0.3f);
    const float TH     = 0.3f;

    // 4 threads duplicate the full state of sample sA (bitwise identical)
    const int sA = tid >> 2;        // 0..31
    const int qk = tid & 3;         // k-quarter: units 16qk..16qk+15
    const int b = blockIdx.x * SPB + sA;

    float x = x0v, mn = x0v, Wsum = 0.0f, pi = pi0, Rv = r0v, p = p0;
    float dwv = dw[b * NSTEPS];
    if (qk == 0) {
        unsigned base = (unsigned)b * 5u;
        out[base + 0] = x0v; out[base + 1] = r0v; out[base + 2] = pi0;
        out[base + 3] = -p0; out[base + 4] = -dp0;
    }

    #pragma unroll 1
    for (int i = 1; i < NSTEPS; ++i) {
        float t = (float)i * DT;
        // ---- fused: gather pi (prev GEMM), store prev row, advance state ----
        if (i > 1) {
            float2 pr = *reinterpret_cast<const float2*>(part + sA * 4);
            pi = b3v + pr.x + pr.y;
            if (qk == 0) {
                unsigned base = ((unsigned)(i - 1) * BATCH + (unsigned)b) * 5u;
                out[base + 0] = x;  out[base + 1] = Rv; out[base + 2] = pi;
                out[base + 3] = -p; out[base + 4] = -dp0;
            }
        }
        {
            float dwi = dwv;
            x = x + x * C_ADT + pi * C_STDT + pi * SIG * dwi;
            mn = fminf(mn, x);
            Wsum += dwi;
            Rv = r0v * __expf(C_R1 * t + BEFF * Wsum);
            p  = p0  * __expf(C_P1 * t - TH * Wsum);
            dwv = dw[b * NSTEPS + i];
        }

        // ---- A: hidden layer -> single fp16 in shared (16 units/thread) ----
        {
            float s0 = 2.0f * t;
            #pragma unroll
            for (int k2 = 0; k2 < 8; ++k2) {
                int k = 16 * qk + 2 * k2;
                float4 wa = sW1q[k];
                float4 wb = sW1q[k + 1];
                float a0 = fmaf(wa.x, s0, wa.w); a0 = fmaf(wa.y, x, a0); a0 = fmaf(wa.z, Rv, a0);
                float a1 = fmaf(wb.x, s0, wb.w); a1 = fmaf(wb.y, x, a1); a1 = fmaf(wb.z, Rv, a1);
                float h0 = tanh_ap(a0), h1v = tanh_ap(a1);
                aH[(8 * qk + k2) * AP_STRIDE + sA] = pack_hf2(h0, h1v);
            }
        }
        __syncthreads();

        // ---- GEMM: warp tile 16 rows x 32 cols (2M x 2N over 4 warps) ----
        {
            float c[4][4];
            #pragma unroll
            for (int nt = 0; nt < 4; ++nt) {
                c[nt][0] = b2a[nt]; c[nt][1] = b2b[nt];
                c[nt][2] = b2a[nt]; c[nt][3] = b2b[nt];
            }
            const int base = 16 * mg;
            #pragma unroll
            for (int kt = 0; kt < 4; ++kt) {
                int r0i = (8 * kt + tg) * AP_STRIDE + base + g;
                int r1i = (8 * kt + tg + 4) * AP_STRIDE + base + g;
                unsigned a0 = aH[r0i], a1 = aH[r0i + 8];
                unsigned a2 = aH[r1i], a3 = aH[r1i + 8];
                #pragma unroll
                for (int nt = 0; nt < 4; ++nt)
                    mma_f16(c[nt], a0, a1, a2, a3, bH0[nt][kt], bH1[nt][kt]);
            }
            // epilogue: tanh, W3 dot, reduce over tg
            float vl = 0.0f, vh = 0.0f;
            #pragma unroll
            for (int nt = 0; nt < 4; ++nt) {
                vl += fmaf(tanh_ap(c[nt][0]), w3a[nt], tanh_ap(c[nt][1]) * w3b[nt]);
                vh += fmaf(tanh_ap(c[nt][2]), w3a[nt], tanh_ap(c[nt][3]) * w3b[nt]);
            }
            vl += __shfl_xor_sync(0xffffffffu, vl, 1);
            vh += __shfl_xor_sync(0xffffffffu, vh, 1);
            vl += __shfl_xor_sync(0xffffffffu, vl, 2);
            vh += __shfl_xor_sync(0xffffffffu, vh, 2);
            if (tg == 0) {
                part[(base + g) * 4 + ng]     = vl;
                part[(base + g + 8) * 4 + ng] = vh;
            }
        }
        __syncthreads();
    }

    // ---- tail: gather pi at t_99, store row 99; final step to t_100 ----
    {
        float2 pr = *reinterpret_cast<const float2*>(part + sA * 4);
        pi = b3v + pr.x + pr.y;
        if (qk == 0) {
            unsigned base = ((unsigned)(NSTEPS - 1) * BATCH + (unsigned)b) * 5u;
            out[base + 0] = x;  out[base + 1] = Rv; out[base + 2] = pi;
            out[base + 3] = -p; out[base + 4] = -dp0;
        }
        float t = (float)NSTEPS * DT;
        float dwi = dwv;
        x = x + x * C_ADT + pi * C_STDT + pi * SIG * dwi;
        mn = fminf(mn, x);
        Wsum += dwi;
        Rv = r0v * __expf(C_R1 * t + BEFF * Wsum);
        p  = p0  * __expf(C_P1 * t - TH * Wsum);
        if (qk == 0) {
            unsigned base = ((unsigned)NSTEPS * BATCH + (unsigned)b) * 5u;
            out[base + 0] = x;  out[base + 1] = Rv; out[base + 2] = pi;
            out[base + 3] = -p; out[base + 4] = -dp0;
        }
    }

    // ---- losses (qk==0 contributes; duplicates elsewhere) ----
    float aa = 0.0f, bb = 0.0f;
    if (qk == 0) {
        float xc  = fmaxf(x, 1e-6f);
        float ux  = Rv * rsqrtf(xc);
        float uv  = 2.0f * Rv * sqrtf(xc);
        float dpn = fmaxf(1e-6f - mn, 0.0f);
        float pen = 100.0f * dpn * dpn;
        aa = p + ux; aa = aa * aa + pen;
        bb = -uv + pen;
    }
    #pragma unroll
    for (int s = 16; s > 0; s >>= 1) {
        aa += __shfl_xor_sync(0xffffffffu, aa, s);
        bb += __shfl_xor_sync(0xffffffffu, bb, s);
    }
    if (lane == 0) { redA[w] = aa; redB[w] = bb; }
    __syncthreads();
    if (tid == 0) {
        g_pA[blockIdx.x] = (redA[0] + redA[1]) + (redA[2] + redA[3]);
        g_pB[blockIdx.x] = (redB[0] + redB[1]) + (redB[2] + redB[3]);
    }
}

__global__ void finalize_kernel(float* __restrict__ out)
{
    __shared__ float rA[NBLK], rB[NBLK];
    int tid = threadIdx.x;
    rA[tid] = g_pA[tid]; rB[tid] = g_pB[tid];
    __syncthreads();
    for (int s = NBLK / 2; s > 0; s >>= 1) {
        if (tid < s) { rA[tid] += rA[tid + s]; rB[tid] += rB[tid + s]; }
        __syncthreads();
    }
    if (tid == 0) {
        float lp  = rA[0] / (float)BATCH;
        float lpi = lp + rB[0] / (float)BATCH;
        unsigned base = (unsigned)(NSTEPS + 1) * BATCH * 5u;
        out[base + 0] = lp;
        out[base + 1] = lpi;
    }
}

extern "C" void kernel_launch(void* const* d_in, const int* in_sizes, int n_in,
                              void* d_out, int out_size)
{
    const float* dw  = (const float*)d_in[0];
    const float* X0  = (const float*)d_in[1];
    const float* R0  = (const float*)d_in[2];
    const float* pW1 = (const float*)d_in[3];  const float* pb1 = (const float*)d_in[4];
    const float* pW2 = (const float*)d_in[5];  const float* pb2 = (const float*)d_in[6];
    const float* pW3 = (const float*)d_in[7];  const float* pb3 = (const float*)d_in[8];
    const float* qW1 = (const float*)d_in[9];  const float* qb1 = (const float*)d_in[10];
    const float* qW2 = (const float*)d_in[11]; const float* qb2 = (const float*)d_in[12];
    const float* qW3 = (const float*)d_in[13]; const float* qb3 = (const float*)d_in[14];
    float* out = (float*)d_out;

    sim_kernel<<<NBLK, 128>>>(dw, X0, R0, pW1, pb1, pW2, pb2, pW3, pb3,
                              qW1, qb1, qW2, qb2, qW3, qb3, out);
    finalize_kernel<<<1, NBLK>>>(out);
}

// round 15
// speedup vs baseline: 1.8917x; 1.8917x over previous
#include <cuda_runtime.h>
#include <cuda_bf16.h>
#include <cuda_fp16.h>

#define HID    64
#define BATCH  16384
#define NSTEPS 100
#define DT     0.01f
#define SPB    64          // samples per block (16 per warp)
#define NBLK   256         // BATCH / SPB
#define AW_STRIDE 40       // words per k2-row in a warp tile: bank(8tg+g) conflict-free reads
#define AW_WARP  (32 * AW_STRIDE)   // 1280 words per warp (mult of 32 -> same bank pattern)

__device__ float g_pA[NBLK];
__device__ float g_pB[NBLK];

__device__ __forceinline__ float exact_tanh(float v) {
    float av = fabsf(v);
    float e  = __expf(-2.0f * av);
    float r  = __fdividef(1.0f - e, 1.0f + e);
    return copysignf(r, v);
}
__device__ __forceinline__ float tanh_ap(float x) {
    float y; asm("tanh.approx.f32 %0, %1;" : "=f"(y) : "f"(x)); return y;
}
__device__ __forceinline__ unsigned pack_hf2(float lo, float hi) {
    __half2 v = __floats2half2_rn(lo, hi);
    return *reinterpret_cast<unsigned*>(&v);
}
__device__ __forceinline__ void mma_f16(float* c,
                                        unsigned a0, unsigned a1, unsigned a2, unsigned a3,
                                        unsigned b0, unsigned b1) {
    asm volatile("mma.sync.aligned.m16n8k16.row.col.f32.f16.f16.f32 "
                 "{%0,%1,%2,%3},{%4,%5,%6,%7},{%8,%9},{%0,%1,%2,%3};"
                 : "+f"(c[0]), "+f"(c[1]), "+f"(c[2]), "+f"(c[3])
                 : "r"(a0), "r"(a1), "r"(a2), "r"(a3), "r"(b0), "r"(b1));
}

__global__ void __launch_bounds__(128) sim_kernel(
    const float* __restrict__ dw,
    const float* __restrict__ X0, const float* __restrict__ R0,
    const float* __restrict__ pW1, const float* __restrict__ pb1,
    const float* __restrict__ pW2, const float* __restrict__ pb2,
    const float* __restrict__ pW3, const float* __restrict__ pb3,
    const float* __restrict__ qW1, const float* __restrict__ qb1,
    const float* __restrict__ qW2, const float* __restrict__ qb2,
    const float* __restrict__ qW3, const float* __restrict__ qb3,
    float* __restrict__ out)
{
    __shared__ __align__(16) float4   sW1q[HID];           // {w_t, w_x, w_r, b1}
    __shared__ __align__(16) unsigned aH[4 * AW_WARP];     // per-warp A tiles (f16x2)
    __shared__ __align__(16) float    spi[4][16];          // per-warp pi results
    __shared__ float  ph1[HID], pd1[HID], ptA[HID], ptB[HID];
    __shared__ float  s_p0, s_dp0, s_pi0, s_b3;
    __shared__ float  redA[4], redB[4];

    const int tid  = threadIdx.x;
    const int lane = tid & 31;
    const int w    = tid >> 5;         // 0..3 : warp owns samples 16w..16w+15
    const int g    = lane >> 2;
    const int tg   = lane & 3;

    const float x0v = X0[0], r0v = R0[0];

    for (int k = tid; k < HID; k += 128)
        sW1q[k] = make_float4(qW1[k], qW1[HID + k], qW1[2 * HID + k], qb1[k]);
    if (tid == 0) s_b3 = qb3[0];

    // ---- B fragments: W2 fp16, all 8 n-tiles per warp, persistent ----
    unsigned bH0[8][4], bH1[8][4];
    float b2a[8], b2b[8], w3a[8], w3b[8];
    #pragma unroll
    for (int nt = 0; nt < 8; ++nt) {
        int n = 8 * nt + g;
        #pragma unroll
        for (int kt = 0; kt < 4; ++kt) {
            int k0 = 16 * kt + 2 * tg;
            bH0[nt][kt] = pack_hf2(qW2[(k0 + 0) * HID + n], qW2[(k0 + 1) * HID + n]);
            bH1[nt][kt] = pack_hf2(qW2[(k0 + 8) * HID + n], qW2[(k0 + 9) * HID + n]);
        }
        int jc = 8 * nt + 2 * tg;
        b2a[nt] = qb2[jc];     b2b[nt] = qb2[jc + 1];
        w3a[nt] = qW3[jc];     w3b[nt] = qW3[jc + 1];
    }

    // ---- scalar prep (p0, dp0, pi0), exact tanh ----
    if (tid < HID) {
        int j = tid;
        float a = pW1[HID + j] * x0v + pW1[2 * HID + j] * r0v + pb1[j];
        float h = exact_tanh(a);
        ph1[j] = h;
        pd1[j] = (1.0f - h * h) * pW1[HID + j];
        float aq = qW1[HID + j] * x0v + qW1[2 * HID + j] * r0v + qb1[j];
        ptA[j] = exact_tanh(aq);
    }
    __syncthreads();
    float pa = 0.0f, qa = 0.0f, db = 0.0f;
    if (tid < HID) {
        int j = tid;
        float acc = pb2[j], dacc = 0.0f, accq = qb2[j];
        #pragma unroll 16
        for (int k = 0; k < HID; ++k) {
            float wv = pW2[k * HID + j];
            acc  += ph1[k] * wv;
            dacc += pd1[k] * wv;
            accq += ptA[k] * qW2[k * HID + j];
        }
        float h2 = exact_tanh(acc);
        float d2 = (1.0f - h2 * h2) * dacc;
        pa = h2 * pW3[j];
        db = d2 * pW3[j];
        qa = exact_tanh(accq) * qW3[j];
    }
    __syncthreads();
    if (tid < HID) { ph1[tid] = pa; pd1[tid] = qa; ptB[tid] = db; }
    __syncthreads();
    if (tid == 0) {
        float s = pb3[0], sd = 0.0f, sq = qb3[0];
        for (int k = 0; k < HID; ++k) { s += ph1[k]; sd += ptB[k]; sq += pd1[k]; }
        s_p0 = s; s_dp0 = sd; s_pi0 = sq;
    }
    __syncthreads();     // last block-wide barrier; hot loop is warp-local

    const float p0  = s_p0;
    const float dp0 = s_dp0;
    const float pi0 = s_pi0;
    const float b3v = s_b3;

    const float C_ADT  = 0.05f * 0.01f;
    const float C_STDT = 0.2f * 0.3f * 0.01f;
    const float SIG    = 0.2f;
    const float BEFF   = 0.1f;
    const float C_R1   = 0.02f - 0.5f * 0.1f * 0.1f;
    const float C_P1   = -(0.05f + 0.5f * 0.3f * 0.3f);
    const float TH     = 0.3f;

    // 2 lanes duplicate the state of local sample sL (bitwise identical)
    const int sL = lane >> 1;          // 0..15
    const int hk = lane & 1;           // k-half: units 32hk..32hk+31
    const int b  = blockIdx.x * SPB + w * 16 + sL;
    unsigned* __restrict__ aW = aH + w * AW_WARP;

    float x = x0v, mn = x0v, Wsum = 0.0f, pi = pi0, Rv = r0v, p = p0;
    float dwv = dw[b * NSTEPS];
    if (hk == 0) {
        unsigned base = (unsigned)b * 5u;
        out[base + 0] = x0v; out[base + 1] = r0v; out[base + 2] = pi0;
        out[base + 3] = -p0; out[base + 4] = -dp0;
    }

    #pragma unroll 1
    for (int i = 1; i < NSTEPS; ++i) {
        float t = (float)i * DT;
        // ---- gather pi (prev step's GEMM), store prev row, advance state ----
        if (i > 1) {
            pi = b3v + spi[w][sL];
            if (hk == 0) {
                unsigned base = ((unsigned)(i - 1) * BATCH + (unsigned)b) * 5u;
                out[base + 0] = x;  out[base + 1] = Rv; out[base + 2] = pi;
                out[base + 3] = -p; out[base + 4] = -dp0;
            }
        }
        {
            float dwi = dwv;
            x = x + x * C_ADT + pi * C_STDT + pi * SIG * dwi;
            mn = fminf(mn, x);
            Wsum += dwi;
            Rv = r0v * __expf(C_R1 * t + BEFF * Wsum);
            p  = p0  * __expf(C_P1 * t - TH * Wsum);
            dwv = dw[b * NSTEPS + i];
        }

        // ---- A: hidden layer -> fp16 into warp-private tile (32 units/lane) ----
        {
            float s0 = 2.0f * t;
            #pragma unroll
            for (int k2 = 0; k2 < 16; ++k2) {
                int k = 32 * hk + 2 * k2;
                float4 wa = sW1q[k];
                float4 wb = sW1q[k + 1];
                float a0 = fmaf(wa.x, s0, wa.w); a0 = fmaf(wa.y, x, a0); a0 = fmaf(wa.z, Rv, a0);
                float a1 = fmaf(wb.x, s0, wb.w); a1 = fmaf(wb.y, x, a1); a1 = fmaf(wb.z, Rv, a1);
                aW[(16 * hk + k2) * AW_STRIDE + sL] = pack_hf2(tanh_ap(a0), tanh_ap(a1));
            }
        }
        __syncwarp();

        // ---- GEMM: warp tile 16 rows x 64 cols, fully warp-local ----
        {
            float c[8][4];
            #pragma unroll
            for (int nt = 0; nt < 8; ++nt) {
                c[nt][0] = b2a[nt]; c[nt][1] = b2b[nt];
                c[nt][2] = b2a[nt]; c[nt][3] = b2b[nt];
            }
            #pragma unroll
            for (int kt = 0; kt < 4; ++kt) {
                int r0i = (8 * kt + tg) * AW_STRIDE + g;
                int r1i = (8 * kt + tg + 4) * AW_STRIDE + g;
                unsigned a0 = aW[r0i], a1 = aW[r0i + 8];
                unsigned a2 = aW[r1i], a3 = aW[r1i + 8];
                #pragma unroll
                for (int nt = 0; nt < 8; ++nt)
                    mma_f16(c[nt], a0, a1, a2, a3, bH0[nt][kt], bH1[nt][kt]);
            }
            // epilogue: tanh, W3 dot over all 64 cols, reduce over tg
            float vl = 0.0f, vh = 0.0f;
            #pragma unroll
            for (int nt = 0; nt < 8; ++nt) {
                vl += fmaf(tanh_ap(c[nt][0]), w3a[nt], tanh_ap(c[nt][1]) * w3b[nt]);
                vh += fmaf(tanh_ap(c[nt][2]), w3a[nt], tanh_ap(c[nt][3]) * w3b[nt]);
            }
            vl += __shfl_xor_sync(0xffffffffu, vl, 1);
            vh += __shfl_xor_sync(0xffffffffu, vh, 1);
            vl += __shfl_xor_sync(0xffffffffu, vl, 2);
            vh += __shfl_xor_sync(0xffffffffu, vh, 2);
            if (tg == 0) {
                spi[w][g]     = vl;    // sample g
                spi[w][g + 8] = vh;    // sample g+8
            }
        }
        __syncwarp();
    }

    // ---- tail: gather pi at t_99, store row 99; final step to t_100 ----
    {
        pi = b3v + spi[w][sL];
        if (hk == 0) {
            unsigned base = ((unsigned)(NSTEPS - 1) * BATCH + (unsigned)b) * 5u;
            out[base + 0] = x;  out[base + 1] = Rv; out[base + 2] = pi;
            out[base + 3] = -p; out[base + 4] = -dp0;
        }
        float t = (float)NSTEPS * DT;
        float dwi = dwv;
        x = x + x * C_ADT + pi * C_STDT + pi * SIG * dwi;
        mn = fminf(mn, x);
        Wsum += dwi;
        Rv = r0v * __expf(C_R1 * t + BEFF * Wsum);
        p  = p0  * __expf(C_P1 * t - TH * Wsum);
        if (hk == 0) {
            unsigned base = ((unsigned)NSTEPS * BATCH + (unsigned)b) * 5u;
            out[base + 0] = x;  out[base + 1] = Rv; out[base + 2] = pi;
            out[base + 3] = -p; out[base + 4] = -dp0;
        }
    }

    // ---- losses (hk==0 contributes; duplicates zeroed) ----
    float aa = 0.0f, bb = 0.0f;
    if (hk == 0) {
        float xc  = fmaxf(x, 1e-6f);
        float ux  = Rv * rsqrtf(xc);
        float uv  = 2.0f * Rv * sqrtf(xc);
        float dpn = fmaxf(1e-6f - mn, 0.0f);
        float pen = 100.0f * dpn * dpn;
        aa = p + ux; aa = aa * aa + pen;
        bb = -uv + pen;
    }
    #pragma unroll
    for (int s = 16; s > 0; s >>= 1) {
        aa += __shfl_xor_sync(0xffffffffu, aa, s);
        bb += __shfl_xor_sync(0xffffffffu, bb, s);
    }
    if (lane == 0) { redA[w] = aa; redB[w] = bb; }
    __syncthreads();
    if (tid == 0) {
        g_pA[blockIdx.x] = (redA[0] + redA[1]) + (redA[2] + redA[3]);
        g_pB[blockIdx.x] = (redB[0] + redB[1]) + (redB[2] + redB[3]);
    }
}

__global__ void finalize_kernel(float* __restrict__ out)
{
    __shared__ float rA[NBLK], rB[NBLK];
    int tid = threadIdx.x;
    rA[tid] = g_pA[tid]; rB[tid] = g_pB[tid];
    __syncthreads();
    for (int s = NBLK / 2; s > 0; s >>= 1) {
        if (tid < s) { rA[tid] += rA[tid + s]; rB[tid] += rB[tid + s]; }
        __syncthreads();
    }
    if (tid == 0) {
        float lp  = rA[0] / (float)BATCH;
        float lpi = lp + rB[0] / (float)BATCH;
        unsigned base = (unsigned)(NSTEPS + 1) * BATCH * 5u;
        out[base + 0] = lp;
        out[base + 1] = lpi;
    }
}

extern "C" void kernel_launch(void* const* d_in, const int* in_sizes, int n_in,
                              void* d_out, int out_size)
{
    const float* dw  = (const float*)d_in[0];
    const float* X0  = (const float*)d_in[1];
    const float* R0  = (const float*)d_in[2];
    const float* pW1 = (const float*)d_in[3];  const float* pb1 = (const float*)d_in[4];
    const float* pW2 = (const float*)d_in[5];  const float* pb2 = (const float*)d_in[6];
    const float* pW3 = (const float*)d_in[7];  const float* pb3 = (const float*)d_in[8];
    const float* qW1 = (const float*)d_in[9];  const float* qb1 = (const float*)d_in[10];
    const float* qW2 = (const float*)d_in[11]; const float* qb2 = (const float*)d_in[12];
    const float* qW3 = (const float*)d_in[13]; const float* qb3 = (const float*)d_in[14];
    float* out = (float*)d_out;

    sim_kernel<<<NBLK, 128>>>(dw, X0, R0, pW1, pb1, pW2, pb2, pW3, pb3,
                              qW1, qb1, qW2, qb2, qW3, qb3, out);
    finalize_kernel<<<1, NBLK>>>(out);
}

// round 16
// speedup vs baseline: 2.7715x; 1.4650x over previous
#include <cuda_runtime.h>
#include <cuda_bf16.h>
#include <cuda_fp16.h>

#define HID    64
#define BATCH  16384
#define NSTEPS 100
#define DT     0.01f
#define SPB    64          // samples per block (16 per warp)
#define NBLK   256         // BATCH / SPB

__device__ float g_pA[NBLK];
__device__ float g_pB[NBLK];

__device__ __forceinline__ float exact_tanh(float v) {
    float av = fabsf(v);
    float e  = __expf(-2.0f * av);
    float r  = __fdividef(1.0f - e, 1.0f + e);
    return copysignf(r, v);
}
__device__ __forceinline__ float tanh_ap(float x) {
    float y; asm("tanh.approx.f32 %0, %1;" : "=f"(y) : "f"(x)); return y;
}
__device__ __forceinline__ unsigned pack_hf2(float lo, float hi) {
    __half2 v = __floats2half2_rn(lo, hi);
    return *reinterpret_cast<unsigned*>(&v);
}
__device__ __forceinline__ void mma_f16(float* c,
                                        unsigned a0, unsigned a1, unsigned a2, unsigned a3,
                                        unsigned b0, unsigned b1) {
    asm volatile("mma.sync.aligned.m16n8k16.row.col.f32.f16.f16.f32 "
                 "{%0,%1,%2,%3},{%4,%5,%6,%7},{%8,%9},{%0,%1,%2,%3};"
                 : "+f"(c[0]), "+f"(c[1]), "+f"(c[2]), "+f"(c[3])
                 : "r"(a0), "r"(a1), "r"(a2), "r"(a3), "r"(b0), "r"(b1));
}

__global__ void __launch_bounds__(128) sim_kernel(
    const float* __restrict__ dw,
    const float* __restrict__ X0, const float* __restrict__ R0,
    const float* __restrict__ pW1, const float* __restrict__ pb1,
    const float* __restrict__ pW2, const float* __restrict__ pb2,
    const float* __restrict__ pW3, const float* __restrict__ pb3,
    const float* __restrict__ qW1, const float* __restrict__ qb1,
    const float* __restrict__ qW2, const float* __restrict__ qb2,
    const float* __restrict__ qW3, const float* __restrict__ qb3,
    float* __restrict__ out)
{
    __shared__ __align__(16) float4 sW1q[HID];           // {w_t, w_x, w_r, b1}
    __shared__ float  ph1[HID], pd1[HID], ptA[HID], ptB[HID];
    __shared__ float  s_p0, s_dp0, s_pi0, s_b3;
    __shared__ float  redA[4], redB[4];

    const int tid  = threadIdx.x;
    const int lane = tid & 31;
    const int w    = tid >> 5;         // warp owns samples 16w..16w+15
    const int g    = lane >> 2;        // row pair (g, g+8)
    const int tg   = lane & 3;         // k-quad within fragment

    const float x0v = X0[0], r0v = R0[0];

    for (int k = tid; k < HID; k += 128)
        sW1q[k] = make_float4(qW1[k], qW1[HID + k], qW1[2 * HID + k], qb1[k]);
    if (tid == 0) s_b3 = qb3[0];

    // ---- B fragments: W2 fp16, all 8 n-tiles per warp, persistent ----
    unsigned bH0[8][4], bH1[8][4];
    float b2a[8], b2b[8], w3a[8], w3b[8];
    #pragma unroll
    for (int nt = 0; nt < 8; ++nt) {
        int n = 8 * nt + g;
        #pragma unroll
        for (int kt = 0; kt < 4; ++kt) {
            int k0 = 16 * kt + 2 * tg;
            bH0[nt][kt] = pack_hf2(qW2[(k0 + 0) * HID + n], qW2[(k0 + 1) * HID + n]);
            bH1[nt][kt] = pack_hf2(qW2[(k0 + 8) * HID + n], qW2[(k0 + 9) * HID + n]);
        }
        int jc = 8 * nt + 2 * tg;
        b2a[nt] = qb2[jc];     b2b[nt] = qb2[jc + 1];
        w3a[nt] = qW3[jc];     w3b[nt] = qW3[jc + 1];
    }

    // ---- scalar prep (p0, dp0, pi0), exact tanh ----
    if (tid < HID) {
        int j = tid;
        float a = pW1[HID + j] * x0v + pW1[2 * HID + j] * r0v + pb1[j];
        float h = exact_tanh(a);
        ph1[j] = h;
        pd1[j] = (1.0f - h * h) * pW1[HID + j];
        float aq = qW1[HID + j] * x0v + qW1[2 * HID + j] * r0v + qb1[j];
        ptA[j] = exact_tanh(aq);
    }
    __syncthreads();
    float pa = 0.0f, qa = 0.0f, db = 0.0f;
    if (tid < HID) {
        int j = tid;
        float acc = pb2[j], dacc = 0.0f, accq = qb2[j];
        #pragma unroll 16
        for (int k = 0; k < HID; ++k) {
            float wv = pW2[k * HID + j];
            acc  += ph1[k] * wv;
            dacc += pd1[k] * wv;
            accq += ptA[k] * qW2[k * HID + j];
        }
        float h2 = exact_tanh(acc);
        float d2 = (1.0f - h2 * h2) * dacc;
        pa = h2 * pW3[j];
        db = d2 * pW3[j];
        qa = exact_tanh(accq) * qW3[j];
    }
    __syncthreads();
    if (tid < HID) { ph1[tid] = pa; pd1[tid] = qa; ptB[tid] = db; }
    __syncthreads();
    if (tid == 0) {
        float s = pb3[0], sd = 0.0f, sq = qb3[0];
        for (int k = 0; k < HID; ++k) { s += ph1[k]; sd += ptB[k]; sq += pd1[k]; }
        s_p0 = s; s_dp0 = sd; s_pi0 = sq;
    }
    __syncthreads();     // last block-wide barrier; hot loop is register-only

    const float p0  = s_p0;
    const float dp0 = s_dp0;
    const float pi0 = s_pi0;
    const float b3v = s_b3;

    const float C_ADT  = 0.05f * 0.01f;
    const float C_STDT = 0.2f * 0.3f * 0.01f;
    const float SIG    = 0.2f;
    const float BEFF   = 0.1f;
    const float C_R1   = 0.02f - 0.5f * 0.1f * 0.1f;
    const float C_P1   = -(0.05f + 0.5f * 0.3f * 0.3f);
    const float TH     = 0.3f;

    // each quad lane duplicates the state of BOTH its rows (samples bA=g, bB=g+8)
    const int bA = blockIdx.x * SPB + w * 16 + g;
    const int bB = bA + 8;

    float xA = x0v, mnA = x0v, WA = 0.0f, RvA = r0v, pA = p0, piA = pi0;
    float xB = x0v, mnB = x0v, WB = 0.0f, RvB = r0v, pB = p0, piB = pi0;
    float dwA = dw[bA * NSTEPS];
    float dwB = dw[bB * NSTEPS];
    float vl = 0.0f, vh = 0.0f;

    if (tg == 0) {
        unsigned base = (unsigned)bA * 5u;
        out[base + 0] = x0v; out[base + 1] = r0v; out[base + 2] = pi0;
        out[base + 3] = -p0; out[base + 4] = -dp0;
    } else if (tg == 1) {
        unsigned base = (unsigned)bB * 5u;
        out[base + 0] = x0v; out[base + 1] = r0v; out[base + 2] = pi0;
        out[base + 3] = -p0; out[base + 4] = -dp0;
    }

    #pragma unroll 1
    for (int i = 1; i < NSTEPS; ++i) {
        float t = (float)i * DT;
        // ---- gather pi (prev GEMM, already all-reduced in quad), store prev ----
        if (i > 1) {
            piA = b3v + vl;
            piB = b3v + vh;
            if (tg == 0) {
                unsigned base = ((unsigned)(i - 1) * BATCH + (unsigned)bA) * 5u;
                out[base + 0] = xA;  out[base + 1] = RvA; out[base + 2] = piA;
                out[base + 3] = -pA; out[base + 4] = -dp0;
            } else if (tg == 1) {
                unsigned base = ((unsigned)(i - 1) * BATCH + (unsigned)bB) * 5u;
                out[base + 0] = xB;  out[base + 1] = RvB; out[base + 2] = piB;
                out[base + 3] = -pB; out[base + 4] = -dp0;
            }
        }
        // ---- state updates (both rows, identical in all quad lanes) ----
        {
            xA = xA + xA * C_ADT + piA * C_STDT + piA * SIG * dwA;
            mnA = fminf(mnA, xA);
            WA += dwA;
            RvA = r0v * __expf(C_R1 * t + BEFF * WA);
            pA  = p0  * __expf(C_P1 * t - TH * WA);
            dwA = dw[bA * NSTEPS + i];

            xB = xB + xB * C_ADT + piB * C_STDT + piB * SIG * dwB;
            mnB = fminf(mnB, xB);
            WB += dwB;
            RvB = r0v * __expf(C_R1 * t + BEFF * WB);
            pB  = p0  * __expf(C_P1 * t - TH * WB);
            dwB = dw[bB * NSTEPS + i];
        }

        // ---- A-fragments computed directly in registers (no smem) ----
        unsigned a0[4], a1[4], a2[4], a3[4];
        {
            float s0 = 2.0f * t;
            #pragma unroll
            for (int kt = 0; kt < 4; ++kt) {
                int u0 = 16 * kt + 2 * tg;
                float4 w0 = sW1q[u0], w1 = sW1q[u0 + 1];
                float4 w2 = sW1q[u0 + 8], w3 = sW1q[u0 + 9];
                float pA0 = fmaf(w0.x, s0, w0.w); pA0 = fmaf(w0.y, xA, pA0); pA0 = fmaf(w0.z, RvA, pA0);
                float pA1 = fmaf(w1.x, s0, w1.w); pA1 = fmaf(w1.y, xA, pA1); pA1 = fmaf(w1.z, RvA, pA1);
                float pB0 = fmaf(w0.x, s0, w0.w); pB0 = fmaf(w0.y, xB, pB0); pB0 = fmaf(w0.z, RvB, pB0);
                float pB1 = fmaf(w1.x, s0, w1.w); pB1 = fmaf(w1.y, xB, pB1); pB1 = fmaf(w1.z, RvB, pB1);
                float qA0 = fmaf(w2.x, s0, w2.w); qA0 = fmaf(w2.y, xA, qA0); qA0 = fmaf(w2.z, RvA, qA0);
                float qA1 = fmaf(w3.x, s0, w3.w); qA1 = fmaf(w3.y, xA, qA1); qA1 = fmaf(w3.z, RvA, qA1);
                float qB0 = fmaf(w2.x, s0, w2.w); qB0 = fmaf(w2.y, xB, qB0); qB0 = fmaf(w2.z, RvB, qB0);
                float qB1 = fmaf(w3.x, s0, w3.w); qB1 = fmaf(w3.y, xB, qB1); qB1 = fmaf(w3.z, RvB, qB1);
                a0[kt] = pack_hf2(tanh_ap(pA0), tanh_ap(pA1));
                a1[kt] = pack_hf2(tanh_ap(pB0), tanh_ap(pB1));
                a2[kt] = pack_hf2(tanh_ap(qA0), tanh_ap(qA1));
                a3[kt] = pack_hf2(tanh_ap(qB0), tanh_ap(qB1));
            }
        }

        // ---- GEMM: 16x64, all operands in registers ----
        {
            float c[8][4];
            #pragma unroll
            for (int nt = 0; nt < 8; ++nt) {
                c[nt][0] = b2a[nt]; c[nt][1] = b2b[nt];
                c[nt][2] = b2a[nt]; c[nt][3] = b2b[nt];
            }
            #pragma unroll
            for (int kt = 0; kt < 4; ++kt)
                #pragma unroll
                for (int nt = 0; nt < 8; ++nt)
                    mma_f16(c[nt], a0[kt], a1[kt], a2[kt], a3[kt], bH0[nt][kt], bH1[nt][kt]);

            // epilogue: tanh, W3 dot, all-reduce over quad -> every lane has vl,vh
            vl = 0.0f; vh = 0.0f;
            #pragma unroll
            for (int nt = 0; nt < 8; ++nt) {
                vl += fmaf(tanh_ap(c[nt][0]), w3a[nt], tanh_ap(c[nt][1]) * w3b[nt]);
                vh += fmaf(tanh_ap(c[nt][2]), w3a[nt], tanh_ap(c[nt][3]) * w3b[nt]);
            }
            vl += __shfl_xor_sync(0xffffffffu, vl, 1);
            vh += __shfl_xor_sync(0xffffffffu, vh, 1);
            vl += __shfl_xor_sync(0xffffffffu, vl, 2);
            vh += __shfl_xor_sync(0xffffffffu, vh, 2);
        }
    }

    // ---- tail: pi at t_99, store row 99; final step to t_100 ----
    {
        piA = b3v + vl;
        piB = b3v + vh;
        if (tg == 0) {
            unsigned base = ((unsigned)(NSTEPS - 1) * BATCH + (unsigned)bA) * 5u;
            out[base + 0] = xA;  out[base + 1] = RvA; out[base + 2] = piA;
            out[base + 3] = -pA; out[base + 4] = -dp0;
        } else if (tg == 1) {
            unsigned base = ((unsigned)(NSTEPS - 1) * BATCH + (unsigned)bB) * 5u;
            out[base + 0] = xB;  out[base + 1] = RvB; out[base + 2] = piB;
            out[base + 3] = -pB; out[base + 4] = -dp0;
        }
        float t = (float)NSTEPS * DT;
        xA = xA + xA * C_ADT + piA * C_STDT + piA * SIG * dwA;
        mnA = fminf(mnA, xA);
        WA += dwA;
        RvA = r0v * __expf(C_R1 * t + BEFF * WA);
        pA  = p0  * __expf(C_P1 * t - TH * WA);
        xB = xB + xB * C_ADT + piB * C_STDT + piB * SIG * dwB;
        mnB = fminf(mnB, xB);
        WB += dwB;
        RvB = r0v * __expf(C_R1 * t + BEFF * WB);
        pB  = p0  * __expf(C_P1 * t - TH * WB);
        if (tg == 0) {
            unsigned base = ((unsigned)NSTEPS * BATCH + (unsigned)bA) * 5u;
            out[base + 0] = xA;  out[base + 1] = RvA; out[base + 2] = piA;
            out[base + 3] = -pA; out[base + 4] = -dp0;
        } else if (tg == 1) {
            unsigned base = ((unsigned)NSTEPS * BATCH + (unsigned)bB) * 5u;
            out[base + 0] = xB;  out[base + 1] = RvB; out[base + 2] = piB;
            out[base + 3] = -pB; out[base + 4] = -dp0;
        }
    }

    // ---- losses: tg0 contributes sample A, tg1 sample B ----
    float aa = 0.0f, bb = 0.0f;
    if (tg == 0) {
        float xc  = fmaxf(xA, 1e-6f);
        float ux  = RvA * rsqrtf(xc);
        float uv  = 2.0f * RvA * sqrtf(xc);
        float dpn = fmaxf(1e-6f - mnA, 0.0f);
        float pen = 100.0f * dpn * dpn;
        aa = pA + ux; aa = aa * aa + pen;
        bb = -uv + pen;
    } else if (tg == 1) {
        float xc  = fmaxf(xB, 1e-6f);
        float ux  = RvB * rsqrtf(xc);
        float uv  = 2.0f * RvB * sqrtf(xc);
        float dpn = fmaxf(1e-6f - mnB, 0.0f);
        float pen = 100.0f * dpn * dpn;
        aa = pB + ux; aa = aa * aa + pen;
        bb = -uv + pen;
    }
    #pragma unroll
    for (int s = 16; s > 0; s >>= 1) {
        aa += __shfl_xor_sync(0xffffffffu, aa, s);
        bb += __shfl_xor_sync(0xffffffffu, bb, s);
    }
    if (lane == 0) { redA[w] = aa; redB[w] = bb; }
    __syncthreads();
    if (tid == 0) {
        g_pA[blockIdx.x] = (redA[0] + redA[1]) + (redA[2] + redA[3]);
        g_pB[blockIdx.x] = (redB[0] + redB[1]) + (redB[2] + redB[3]);
    }
}

__global__ void finalize_kernel(float* __restrict__ out)
{
    __shared__ float rA[NBLK], rB[NBLK];
    int tid = threadIdx.x;
    rA[tid] = g_pA[tid]; rB[tid] = g_pB[tid];
    __syncthreads();
    for (int s = NBLK / 2; s > 0; s >>= 1) {
        if (tid < s) { rA[tid] += rA[tid + s]; rB[tid] += rB[tid + s]; }
        __syncthreads();
    }
    if (tid == 0) {
        float lp  = rA[0] / (float)BATCH;
        float lpi = lp + rB[0] / (float)BATCH;
        unsigned base = (unsigned)(NSTEPS + 1) * BATCH * 5u;
        out[base + 0] = lp;
        out[base + 1] = lpi;
    }
}

extern "C" void kernel_launch(void* const* d_in, const int* in_sizes, int n_in,
                              void* d_out, int out_size)
{
    const float* dw  = (const float*)d_in[0];
    const float* X0  = (const float*)d_in[1];
    const float* R0  = (const float*)d_in[2];
    const float* pW1 = (const float*)d_in[3];  const float* pb1 = (const float*)d_in[4];
    const float* pW2 = (const float*)d_in[5];  const float* pb2 = (const float*)d_in[6];
    const float* pW3 = (const float*)d_in[7];  const float* pb3 = (const float*)d_in[8];
    const float* qW1 = (const float*)d_in[9];  const float* qb1 = (const float*)d_in[10];
    const float* qW2 = (const float*)d_in[11]; const float* qb2 = (const float*)d_in[12];
    const float* qW3 = (const float*)d_in[13]; const float* qb3 = (const float*)d_in[14];
    float* out = (float*)d_out;

    sim_kernel<<<NBLK, 128>>>(dw, X0, R0, pW1, pb1, pW2, pb2, pW3, pb3,
                              qW1, qb1, qW2, qb2, qW3, qb3, out);
    finalize_kernel<<<1, NBLK>>>(out);
}